// round 6
// baseline (speedup 1.0000x reference)
#include <cuda_runtime.h>
#include <math.h>

// Problem constants (B=4, S=2048, D_IN=1024, D_OUT=1024, E=8, K=2)
#define BTOK    8192
#define DIN     1024
#define DOUT    1024
#define NE      8
#define NROW    24          // 8 gate rows + 16 expert rows (e, o in {0,1})
#define SPLITK  16
#define KS      (DIN / SPLITK)   // 64 k per block
#define TOKB    256         // tokens per GEMM block (8 warps, lane+warp = token)
#define GTH     256
#define XSS     68          // padded row stride: banks 4*lane within 8-lane phase

#define GEMM_SMEM ((TOKB + NROW) * XSS * 4)   // 76160 B

// Transposed partials: scratch[(split*NROW + row)*BTOK + token]
__device__ float g_scratch[SPLITK * NROW * BTOK];   // 12.6 MB

__device__ __forceinline__ unsigned long long fma2(unsigned long long a,
                                                   unsigned long long b,
                                                   unsigned long long c) {
    unsigned long long d;
    asm("fma.rn.f32x2 %0, %1, %2, %3;" : "=l"(d) : "l"(a), "l"(b), "l"(c));
    return d;
}
__device__ __forceinline__ void unpack2(unsigned long long v, float& lo, float& hi) {
    asm("mov.b64 {%0, %1}, %2;" : "=f"(lo), "=f"(hi) : "l"(v));
}

// ---------------------------------------------------------------------------
// Kernel 1: split-K skinny GEMM. Block = 256 tokens x 64 k. thread = token.
// Weights broadcast from smem; packed f32x2 FMA over adjacent k.
// ---------------------------------------------------------------------------
__global__ __launch_bounds__(GTH)
void moe_gemm_kernel(const float* __restrict__ x,
                     const float* __restrict__ gate_w,
                     const float* __restrict__ expert_w)
{
    extern __shared__ float smem[];
    float (*xs)[XSS] = (float(*)[XSS])smem;                  // [256][68]
    float (*ws)[XSS] = (float(*)[XSS])(smem + TOKB * XSS);   // [24][68]

    const int tid   = threadIdx.x;
    const int split = blockIdx.x & (SPLITK - 1);
    const int tb    = blockIdx.x >> 4;
    const int tok0  = tb * TOKB;
    const int kbase = split * KS;

    // ---- load x tile: 256 tokens x 64 floats = 4096 float4 (coalesced) ----
    #pragma unroll
    for (int j = 0; j < (TOKB * KS) / (4 * GTH); j++) {      // 16
        int i  = tid + j * GTH;
        int m  = i >> 4;                 // token
        int f4 = (i & 15) << 2;          // float offset in 64-float row
        float4 v = *(const float4*)(x + (size_t)(tok0 + m) * DIN + kbase + f4);
        *(float4*)&xs[m][f4] = v;
    }

    // ---- load weight tile: 24 rows x 64 floats = 384 float4 ----
    #pragma unroll
    for (int j = 0; j < 2; j++) {
        int i = tid + j * GTH;
        if (i < (NROW * KS) / 4) {
            int row = i >> 4;
            int f4  = (i & 15) << 2;
            const float* src = (row < NE)
                ? (gate_w + (size_t)row * DIN)
                : (expert_w + ((size_t)(((row - NE) >> 1) * DOUT + ((row - NE) & 1))) * DIN);
            float4 v = *(const float4*)(src + kbase + f4);
            *(float4*)&ws[row][f4] = v;
        }
    }

    __syncthreads();

    // ---- compute: thread = token, all 24 rows, FFMA2 over k-pairs ----
    const float* xr = &xs[tid][0];

    unsigned long long acc[NROW];
    #pragma unroll
    for (int r = 0; r < NROW; r++) acc[r] = 0ULL;

    #pragma unroll 4
    for (int kk = 0; kk < KS; kk += 4) {
        ulonglong2 xv = *(const ulonglong2*)(xr + kk);       // (x_k,x_k+1),(x_k+2,x_k+3)
        #pragma unroll
        for (int r = 0; r < NROW; r++) {
            ulonglong2 wv = *(const ulonglong2*)(&ws[r][kk]);  // warp-broadcast
            acc[r] = fma2(xv.x, wv.x, acc[r]);
            acc[r] = fma2(xv.y, wv.y, acc[r]);
        }
    }

    // ---- write partials, coalesced: [split][row][token] ----
    const int token = tok0 + tid;
    #pragma unroll
    for (int r = 0; r < NROW; r++) {
        float lo, hi;
        unpack2(acc[r], lo, hi);
        g_scratch[((size_t)(split * NROW + r)) * BTOK + token] = lo + hi;
    }
}

// ---------------------------------------------------------------------------
// Kernel 2: parallel reduce + gating epilogue + broadcast write
// ---------------------------------------------------------------------------
#define ETOK 16
#define ETH  256
#define PST  26

__global__ __launch_bounds__(ETH)
void moe_epilogue_kernel(const float* __restrict__ gate_b,
                         const float* __restrict__ ebias,
                         const float* __restrict__ expert_b,
                         float* __restrict__ out,
                         float* __restrict__ idx_out)
{
    __shared__ float Pp[SPLITK][ETOK][PST];   // 26.6 KB
    __shared__ float Pfin[ETOK][PST];
    __shared__ float wtok[ETOK];

    const int tid  = threadIdx.x;
    const int tok0 = blockIdx.x * ETOK;

    // ---- Phase A: thread = (token, split); 24 coalesced loads each ----
    {
        const int token = tid & (ETOK - 1);
        const int slot  = tid >> 4;          // 0..15 = split
        const float* src = g_scratch + (size_t)(slot * NROW) * BTOK + tok0 + token;
        float* dst = &Pp[slot][token][0];
        #pragma unroll
        for (int r = 0; r < NROW; r++)
            dst[r] = src[(size_t)r * BTOK];
    }
    __syncthreads();

    // ---- Phase B: 384 cells (16 tok x 24 rows), <=2 per thread ----
    #pragma unroll
    for (int c = 0; c < 2; c++) {
        int cell = tid + c * ETH;
        if (cell < ETOK * NROW) {
            int token = cell / NROW;
            int r     = cell - token * NROW;
            float s = 0.f;
            #pragma unroll
            for (int sp = 0; sp < SPLITK; sp++)
                s += Pp[sp][token][r];
            Pfin[token][r] = s;
        }
    }
    __syncthreads();

    // ---- Phase C: gating (threads 0..15) ----
    if (tid < ETOK) {
        const float* Pm = &Pfin[tid][0];
        float l[NE];
        #pragma unroll
        for (int e = 0; e < NE; e++)
            l[e] = Pm[e] + gate_b[e] + ebias[e];

        int e0 = 0; float b0 = l[0];
        #pragma unroll
        for (int e = 1; e < NE; e++)
            if (l[e] > b0) { b0 = l[e]; e0 = e; }
        int e1 = -1; float b1 = -INFINITY;
        #pragma unroll
        for (int e = 0; e < NE; e++) {
            if (e == e0) continue;
            if (l[e] > b1) { b1 = l[e]; e1 = e; }
        }

        float p0 = 1.f / (1.f + expf(-b0));
        float p1 = 1.f / (1.f + expf(-b1));
        float inv = 1.f / (p0 + p1);

        float v0 = Pm[NE + e0 * 2 + 0] + expert_b[(size_t)e0 * DOUT + 0];
        float v1 = Pm[NE + e1 * 2 + 1] + expert_b[(size_t)e1 * DOUT + 1];
        wtok[tid] = (v0 * p0 + v1 * p1) * inv;

        if (idx_out) {
            idx_out[(size_t)(tok0 + tid) * 2 + 0] = (float)e0;
            idx_out[(size_t)(tok0 + tid) * 2 + 1] = (float)e1;
        }
    }
    __syncthreads();

    // ---- Phase D: broadcast write, 256 threads x float4 = 1024 floats/token ----
    const int fo = tid << 2;
    #pragma unroll 4
    for (int m = 0; m < ETOK; m++) {
        float v = wtok[m];
        float4 v4 = make_float4(v, v, v, v);
        *(float4*)(out + (size_t)(tok0 + m) * DOUT + fo) = v4;
    }
}

extern "C" void kernel_launch(void* const* d_in, const int* in_sizes, int n_in,
                              void* d_out, int out_size)
{
    const float* x        = (const float*)d_in[0];
    const float* gate_w   = (const float*)d_in[1];
    const float* gate_b   = (const float*)d_in[2];
    const float* ebias    = (const float*)d_in[3];
    const float* expert_w = (const float*)d_in[4];
    const float* expert_b = (const float*)d_in[5];
    float* out = (float*)d_out;

    float* idx_out = nullptr;
    long long base = (long long)BTOK * DOUT;
    if ((long long)out_size >= base + (long long)BTOK * 2)
        idx_out = out + base;

    cudaFuncSetAttribute(moe_gemm_kernel,
                         cudaFuncAttributeMaxDynamicSharedMemorySize, GEMM_SMEM);

    moe_gemm_kernel<<<(BTOK / TOKB) * SPLITK, GTH, GEMM_SMEM>>>(x, gate_w, expert_w);
    moe_epilogue_kernel<<<BTOK / ETOK, ETH>>>(gate_b, ebias, expert_b,
                                              out, idx_out);
}